// round 6
// baseline (speedup 1.0000x reference)
#include <cuda_runtime.h>
#include <cstdint>

#define MUL 32
#define N_NODES 50000
#define E_FEAT 224           // 32 + 96 + 96
#define MAX_E  2097152       // capacity of static CSR scratch (E=800k fits)

__device__ int g_idx_is_64;            // 1 if index buffers are int64, 0 if int32
__device__ int g_cnt[N_NODES + 1];     // histogram -> exclusive offsets (cursor)
__device__ int g_off[N_NODES + 1];     // stable copy of offsets (+ total at [N])
__device__ int g_eid[MAX_E];           // edge ids grouped by dst
__device__ int g_srt[MAX_E];           // src node per sorted slot

__device__ __forceinline__ long long load_index(const void* p, int e, int is64) {
    if (is64) return ((const long long*)p)[e];
    return (long long)(__ldcs((const int*)p + e));
}

// ───────────────────────── sort passes ─────────────────────────

__global__ void k_reset(const unsigned int* __restrict__ dw,
                        const unsigned int* __restrict__ sw) {
    int i = blockIdx.x * blockDim.x + threadIdx.x;
    if (i <= N_NODES) g_cnt[i] = 0;
    if (blockIdx.x == 0 && threadIdx.x == 0) {
        // int64 little-endian values < 50000 -> every odd 32-bit word is 0.
        int is64 = 1;
        #pragma unroll
        for (int k = 0; k < 32; k++) {
            if (dw[2 * k + 1] != 0u || sw[2 * k + 1] != 0u) { is64 = 0; break; }
        }
        g_idx_is_64 = is64;
    }
}

__global__ void k_hist(const void* __restrict__ edge_dst, int E) {
    int e = blockIdx.x * blockDim.x + threadIdx.x;
    if (e >= E) return;
    long long d = load_index(edge_dst, e, g_idx_is_64);
    if ((unsigned long long)d < (unsigned long long)N_NODES)
        atomicAdd(&g_cnt[(int)d], 1);
}

// Exclusive scan of g_cnt[0..N_NODES) into g_off and g_cnt (cursor). One block.
__global__ void k_scan() {
    __shared__ int wsum[32];
    __shared__ int sbase;
    const int t = threadIdx.x, lane = t & 31, wid = t >> 5;
    if (t == 0) sbase = 0;
    __syncthreads();
    for (int c = 0; c < N_NODES; c += 1024) {
        int i = c + t;
        int v = (i < N_NODES) ? g_cnt[i] : 0;
        int incl = v;
        #pragma unroll
        for (int o = 1; o < 32; o <<= 1) {
            int y = __shfl_up_sync(0xffffffffu, incl, o);
            if (lane >= o) incl += y;
        }
        if (lane == 31) wsum[wid] = incl;
        __syncthreads();
        if (wid == 0) {
            int wv = wsum[lane];
            int wi = wv;
            #pragma unroll
            for (int o = 1; o < 32; o <<= 1) {
                int y = __shfl_up_sync(0xffffffffu, wi, o);
                if (lane >= o) wi += y;
            }
            wsum[lane] = wi - wv;   // exclusive base per warp
        }
        __syncthreads();
        int excl = sbase + wsum[wid] + incl - v;
        if (i < N_NODES) { g_off[i] = excl; g_cnt[i] = excl; }
        __syncthreads();
        if (t == 1023) sbase = excl + v;   // running total through this chunk
        __syncthreads();
    }
    if (t == 0) g_off[N_NODES] = sbase;
}

__global__ void k_scatter(const void* __restrict__ edge_dst,
                          const void* __restrict__ edge_src, int E) {
    int e = blockIdx.x * blockDim.x + threadIdx.x;
    if (e >= E) return;
    const int is64 = g_idx_is_64;
    long long d = load_index(edge_dst, e, is64);
    if ((unsigned long long)d >= (unsigned long long)N_NODES) return;
    long long s = load_index(edge_src, e, is64);
    int slot = atomicAdd(&g_cnt[(int)d], 1);
    g_eid[slot] = e;
    g_srt[slot] = (int)s;
}

// ───────────────────────── gather phase ─────────────────────────

__global__ __launch_bounds__(256)
void k_gather(const float* __restrict__ x,
              const float* __restrict__ attr,
              const float* __restrict__ w,
              float* __restrict__ out) {
    constexpr float INV_S2 = 0.70710678118654752f;
    constexpr float INV_S3 = 0.57735026918962576f;

    __shared__ float sf[8][E_FEAT];

    const int warp = threadIdx.x >> 5;
    const int lane = threadIdx.x & 31;
    const int n = blockIdx.x * 8 + warp;
    if (n >= N_NODES) return;

    const int start = g_off[n];
    const int end   = g_off[n + 1];

    float acc0 = 0.f;
    float acc1a = 0.f, acc1b = 0.f, acc1c = 0.f;
    float acc2a = 0.f, acc2b = 0.f, acc2c = 0.f;

    for (int base = start; base < end; base += 32) {
        int m = end - base; if (m > 32) m = 32;
        int eid = 0, sn = -1;
        if (lane < m) {
            eid = __ldcs(g_eid + base + lane);
            sn  = __ldcs(g_srt + base + lane);
        }
        for (int k = 0; k < m; k++) {
            const int e = __shfl_sync(0xffffffffu, eid, k);
            const int s = __shfl_sync(0xffffffffu, sn, k);
            if ((unsigned)s >= (unsigned)N_NODES) continue;

            const float* __restrict__ xr = x + (size_t)s * (4 * MUL);
            const float xs0 = __ldg(xr + lane);
            const float x1a = __ldg(xr + 32 + lane * 3 + 0);
            const float x1b = __ldg(xr + 32 + lane * 3 + 1);
            const float x1c = __ldg(xr + 32 + lane * 3 + 2);

            const float4 a = __ldcs(reinterpret_cast<const float4*>(attr + (size_t)e * 4));

            const float* __restrict__ wr = w + (size_t)e * (5 * MUL);
            const float w0 = __ldcs(wr + lane);
            const float w1 = __ldcs(wr + 32 + lane);
            const float w2 = __ldcs(wr + 64 + lane);
            const float w3 = __ldcs(wr + 96 + lane);
            const float w4 = __ldcs(wr + 128 + lane);

            const float dot = x1a * a.y + x1b * a.z + x1c * a.w;

            acc0  += INV_S2 * (w0 * xs0 * a.x + w3 * (INV_S3 * dot));
            acc1a += INV_S2 * (w1 * xs0 * a.y + w2 * x1a * a.x);
            acc1b += INV_S2 * (w1 * xs0 * a.z + w2 * x1b * a.x);
            acc1c += INV_S2 * (w1 * xs0 * a.w + w2 * x1c * a.x);
            acc2a += INV_S2 * w4 * (x1b * a.w - x1c * a.z);
            acc2b += INV_S2 * w4 * (x1c * a.y - x1a * a.w);
            acc2c += INV_S2 * w4 * (x1a * a.z - x1b * a.y);
        }
    }

    // One transpose per NODE (amortized), then plain coalesced stores. No atomics.
    sf[warp][lane]               = acc0;
    sf[warp][32 + lane * 3 + 0]  = acc1a;
    sf[warp][32 + lane * 3 + 1]  = acc1b;
    sf[warp][32 + lane * 3 + 2]  = acc1c;
    sf[warp][128 + lane * 3 + 0] = acc2a;
    sf[warp][128 + lane * 3 + 1] = acc2b;
    sf[warp][128 + lane * 3 + 2] = acc2c;
    __syncwarp();

    float* __restrict__ ob = out + (size_t)n * E_FEAT;
    float4 v0 = *reinterpret_cast<float4*>(&sf[warp][lane * 4]);
    *reinterpret_cast<float4*>(ob + lane * 4) = v0;
    const int idx = lane + 32;
    if (idx < 56) {
        float4 v1 = *reinterpret_cast<float4*>(&sf[warp][idx * 4]);
        *reinterpret_cast<float4*>(ob + idx * 4) = v1;
    }
}

// ───────────────── fallback (E > MAX_E): round-4 atomic path ─────────────────

__device__ __forceinline__ void red_add_v4(float* addr, float4 v) {
    asm volatile("red.global.add.v4.f32 [%0], {%1,%2,%3,%4};"
                 :: "l"(addr), "f"(v.x), "f"(v.y), "f"(v.z), "f"(v.w)
                 : "memory");
}

__global__ void k_zero(float4* __restrict__ out, int n4) {
    int i = blockIdx.x * blockDim.x + threadIdx.x;
    if (i < n4) out[i] = make_float4(0.f, 0.f, 0.f, 0.f);
}

__global__ __launch_bounds__(256)
void k_scatter_atomic(const float* __restrict__ x, const float* __restrict__ attr,
                      const float* __restrict__ w, const void* __restrict__ edge_dst,
                      const void* __restrict__ edge_src, float* __restrict__ out, int E) {
    constexpr float INV_S2 = 0.70710678118654752f;
    constexpr float INV_S3 = 0.57735026918962576f;
    __shared__ float sf[8][E_FEAT];
    const int warp = threadIdx.x >> 5, lane = threadIdx.x & 31;
    const int e = blockIdx.x * 8 + warp;
    if (e >= E) return;
    const int is64 = g_idx_is_64;
    const long long s = load_index(edge_src, e, is64);
    const long long d = load_index(edge_dst, e, is64);
    if ((unsigned long long)s >= (unsigned long long)N_NODES ||
        (unsigned long long)d >= (unsigned long long)N_NODES) return;
    const float* xr = x + s * (4 * MUL);
    const float xs0 = __ldg(xr + lane);
    const float x1a = __ldg(xr + 32 + lane * 3 + 0);
    const float x1b = __ldg(xr + 32 + lane * 3 + 1);
    const float x1c = __ldg(xr + 32 + lane * 3 + 2);
    const float4 a = __ldcs(reinterpret_cast<const float4*>(attr + (size_t)e * 4));
    const float* wr = w + (size_t)e * (5 * MUL);
    const float w0 = __ldcs(wr + lane), w1 = __ldcs(wr + 32 + lane),
                w2 = __ldcs(wr + 64 + lane), w3 = __ldcs(wr + 96 + lane),
                w4 = __ldcs(wr + 128 + lane);
    const float dot = x1a * a.y + x1b * a.z + x1c * a.w;
    sf[warp][lane]               = INV_S2 * (w0 * xs0 * a.x + w3 * (INV_S3 * dot));
    sf[warp][32 + lane * 3 + 0]  = INV_S2 * (w1 * xs0 * a.y + w2 * x1a * a.x);
    sf[warp][32 + lane * 3 + 1]  = INV_S2 * (w1 * xs0 * a.z + w2 * x1b * a.x);
    sf[warp][32 + lane * 3 + 2]  = INV_S2 * (w1 * xs0 * a.w + w2 * x1c * a.x);
    sf[warp][128 + lane * 3 + 0] = INV_S2 * w4 * (x1b * a.w - x1c * a.z);
    sf[warp][128 + lane * 3 + 1] = INV_S2 * w4 * (x1c * a.y - x1a * a.w);
    sf[warp][128 + lane * 3 + 2] = INV_S2 * w4 * (x1a * a.z - x1b * a.y);
    __syncwarp();
    float* ob = out + d * E_FEAT;
    float4 v0 = *reinterpret_cast<float4*>(&sf[warp][lane * 4]);
    red_add_v4(ob + lane * 4, v0);
    int idx = lane + 32;
    if (idx < 56) {
        float4 v1 = *reinterpret_cast<float4*>(&sf[warp][idx * 4]);
        red_add_v4(ob + idx * 4, v1);
    }
}

// ───────────────────────── launch ─────────────────────────

extern "C" void kernel_launch(void* const* d_in, const int* in_sizes, int n_in,
                              void* d_out, int out_size) {
    // Identify inputs by element count (robust to harness input ordering):
    //   edge_weight : E*160 (largest), edge_attr : E*4, edge_dst/src : E (dst first), x : remainder
    const float* x = nullptr;
    const float* edge_attr = nullptr;
    const float* edge_wt = nullptr;
    const void* e_dst = nullptr;
    const void* e_src = nullptr;

    long long sz_w = 0;
    for (int i = 0; i < n_in; i++)
        if ((long long)in_sizes[i] > sz_w) sz_w = in_sizes[i];

    const long long E_ll = sz_w / 160;
    const long long sz_attr = E_ll * 4;
    const long long sz_idx  = E_ll;

    for (int i = 0; i < n_in; i++) {
        long long sz = in_sizes[i];
        if (sz == sz_w && !edge_wt)            edge_wt   = (const float*)d_in[i];
        else if (sz == sz_attr && !edge_attr)  edge_attr = (const float*)d_in[i];
        else if (sz == sz_idx) {
            if (!e_dst)      e_dst = d_in[i];
            else if (!e_src) e_src = d_in[i];
        }
        else if (!x)                           x = (const float*)d_in[i];
    }

    float* out = (float*)d_out;
    const int E = (int)E_ll;

    if (E <= MAX_E) {
        // CSR two-phase: build (reset/hist/scan/scatter), then gather (no atomics).
        k_reset<<<(N_NODES + 256) / 256, 256>>>((const unsigned int*)e_dst,
                                                (const unsigned int*)e_src);
        k_hist<<<(E + 255) / 256, 256>>>(e_dst, E);
        k_scan<<<1, 1024>>>();
        k_scatter<<<(E + 255) / 256, 256>>>(e_dst, e_src, E);
        k_gather<<<(N_NODES + 7) / 8, 256>>>(x, edge_attr, edge_wt, out);
    } else {
        // Fallback: atomic scatter path.
        k_reset<<<(N_NODES + 256) / 256, 256>>>((const unsigned int*)e_dst,
                                                (const unsigned int*)e_src);
        const int n4 = out_size / 4;
        k_zero<<<(n4 + 255) / 256, 256>>>((float4*)out, n4);
        k_scatter_atomic<<<(E + 7) / 8, 256>>>(x, edge_attr, edge_wt, e_dst, e_src, out, E);
    }
}

// round 7
// speedup vs baseline: 1.5450x; 1.5450x over previous
#include <cuda_runtime.h>
#include <cstdint>

#define MUL 32
#define N_NODES 50000
#define E_FEAT 224           // 32 + 96 + 96
#define EDGES_PER_BLOCK 8    // 256 threads / 32

__device__ int g_idx_is_64;  // 1 if index buffers are int64, 0 if int32

__device__ __forceinline__ void red_add_v4(float* addr, float4 v) {
    asm volatile("red.global.add.v4.f32 [%0], {%1,%2,%3,%4};"
                 :: "l"(addr), "f"(v.x), "f"(v.y), "f"(v.z), "f"(v.w)
                 : "memory");
}

__device__ __forceinline__ long long load_index(const void* p, int e, int is64) {
    if (is64) return ((const long long*)p)[e];
    return (long long)(__ldcs((const int*)p + e));
}

__device__ __forceinline__ float sel4(float t0, float t1, float t2, float t3, int c) {
    float lo = (c & 1) ? t1 : t0;
    float hi = (c & 1) ? t3 : t2;
    return (c & 2) ? hi : lo;
}

// Fused: zero the output AND (thread 0 of block 0) detect index dtype.
__global__ void init_kernel(float4* __restrict__ out, int n4,
                            const unsigned int* __restrict__ dw,
                            const unsigned int* __restrict__ sw) {
    int i = blockIdx.x * blockDim.x + threadIdx.x;
    if (i < n4) out[i] = make_float4(0.f, 0.f, 0.f, 0.f);
    if (blockIdx.x == 0 && threadIdx.x == 0) {
        // int64 little-endian values < 50000 -> every odd 32-bit word is 0.
        int is64 = 1;
        #pragma unroll
        for (int k = 0; k < 32; k++) {
            if (dw[2 * k + 1] != 0u || sw[2 * k + 1] != 0u) { is64 = 0; break; }
        }
        g_idx_is_64 = is64;
    }
}

__global__ __launch_bounds__(256)
void tp_scatter_kernel(const float* __restrict__ x,
                       const float* __restrict__ attr,
                       const float* __restrict__ w,
                       const void* __restrict__ edge_dst,
                       const void* __restrict__ edge_src,
                       float* __restrict__ out,
                       int E) {
    constexpr float INV_S2 = 0.70710678118654752f;
    constexpr float INV_S3 = 0.57735026918962576f;

    __shared__ float sf[EDGES_PER_BLOCK][E_FEAT];   // output transpose staging

    const int warp = threadIdx.x >> 5;
    const int lane = threadIdx.x & 31;
    const int e = blockIdx.x * EDGES_PER_BLOCK + warp;
    if (e >= E) return;

    const int is64 = g_idx_is_64;
    const long long s = load_index(edge_src, e, is64);
    const long long d = load_index(edge_dst, e, is64);
    // Safety guard (valid inputs always in range).
    if ((unsigned long long)s >= (unsigned long long)N_NODES ||
        (unsigned long long)d >= (unsigned long long)N_NODES) return;

    // ── x row: ONE coalesced LDG.128 per lane (4 L1 wavefronts vs 10 for the
    //    strided scalar gather), redistributed via the shuffle network (no L1). ──
    const float4 v = __ldg(reinterpret_cast<const float4*>(x + s * (4 * MUL)) + lane);

    // xs0 = flat[lane]: src lane = lane>>2, component = lane&3
    const unsigned FULL = 0xffffffffu;
    {
    }
    const int src0 = lane >> 2;
    const float s0x = __shfl_sync(FULL, v.x, src0);
    const float s0y = __shfl_sync(FULL, v.y, src0);
    const float s0z = __shfl_sync(FULL, v.z, src0);
    const float s0w = __shfl_sync(FULL, v.w, src0);
    const float xs0 = sel4(s0x, s0y, s0z, s0w, lane & 3);

    // x1[lane][0..2] = flat[32+3*lane .. 34+3*lane]; spans src lanes p, p+1
    const int j  = 32 + 3 * lane;
    const int p  = j >> 2;
    const int o  = j & 3;
    const float a0 = __shfl_sync(FULL, v.x, p);
    const float a1 = __shfl_sync(FULL, v.y, p);
    const float a2 = __shfl_sync(FULL, v.z, p);
    const float a3 = __shfl_sync(FULL, v.w, p);
    const float b0 = __shfl_sync(FULL, v.x, p + 1);   // p+1 never selected when it wraps (lane 31 -> o=1)
    const float b1 = __shfl_sync(FULL, v.y, p + 1);
    const float x1a = sel4(a0, a1, a2, a3, o);
    const float x1b = sel4(a1, a2, a3, b0, o);
    const float x1c = sel4(a2, a3, b0, b1, o);

    // attr / weights streamed once: evict-first.
    const float4 a = __ldcs(reinterpret_cast<const float4*>(attr + (size_t)e * 4));

    const float* __restrict__ wr = w + (size_t)e * (5 * MUL);
    const float w0 = __ldcs(wr + lane);
    const float w1 = __ldcs(wr + 32 + lane);
    const float w2 = __ldcs(wr + 64 + lane);
    const float w3 = __ldcs(wr + 96 + lane);
    const float w4 = __ldcs(wr + 128 + lane);

    const float dot = x1a * a.y + x1b * a.z + x1c * a.w;

    const float o0  = INV_S2 * (w0 * xs0 * a.x + w3 * (INV_S3 * dot));
    const float o1a = INV_S2 * (w1 * xs0 * a.y + w2 * x1a * a.x);
    const float o1b = INV_S2 * (w1 * xs0 * a.z + w2 * x1b * a.x);
    const float o1c = INV_S2 * (w1 * xs0 * a.w + w2 * x1c * a.x);

    // cross(xs1, a1)
    const float c0 = x1b * a.w - x1c * a.z;
    const float c1 = x1c * a.y - x1a * a.w;
    const float c2 = x1a * a.z - x1b * a.y;
    const float o2a = INV_S2 * w4 * c0;
    const float o2b = INV_S2 * w4 * c1;
    const float o2c = INV_S2 * w4 * c2;

    // Stage outputs in output layout (conflict-free: 3u+i mod 32 is a bijection per i)
    sf[warp][lane]               = o0;
    sf[warp][32 + lane * 3 + 0]  = o1a;
    sf[warp][32 + lane * 3 + 1]  = o1b;
    sf[warp][32 + lane * 3 + 2]  = o1c;
    sf[warp][128 + lane * 3 + 0] = o2a;
    sf[warp][128 + lane * 3 + 1] = o2b;
    sf[warp][128 + lane * 3 + 2] = o2c;
    __syncwarp();

    float* __restrict__ ob = out + d * E_FEAT;   // d*896 bytes: 16B-aligned

    // 224 floats = 56 float4 vector-REDs
    float4 v0 = *reinterpret_cast<float4*>(&sf[warp][lane * 4]);
    red_add_v4(ob + lane * 4, v0);
    const int idx = lane + 32;
    if (idx < 56) {
        float4 v1 = *reinterpret_cast<float4*>(&sf[warp][idx * 4]);
        red_add_v4(ob + idx * 4, v1);
    }
}

extern "C" void kernel_launch(void* const* d_in, const int* in_sizes, int n_in,
                              void* d_out, int out_size) {
    // Identify inputs by element count (robust to harness input ordering):
    //   edge_weight : E*160 (largest), edge_attr : E*4, edge_dst/src : E (dst first), x : remainder
    const float* x = nullptr;
    const float* edge_attr = nullptr;
    const float* edge_wt = nullptr;
    const void* e_dst = nullptr;
    const void* e_src = nullptr;

    long long sz_w = 0;
    for (int i = 0; i < n_in; i++)
        if ((long long)in_sizes[i] > sz_w) sz_w = in_sizes[i];

    const long long E_ll = sz_w / 160;
    const long long sz_attr = E_ll * 4;
    const long long sz_idx  = E_ll;

    for (int i = 0; i < n_in; i++) {
        long long sz = in_sizes[i];
        if (sz == sz_w && !edge_wt)            edge_wt   = (const float*)d_in[i];
        else if (sz == sz_attr && !edge_attr)  edge_attr = (const float*)d_in[i];
        else if (sz == sz_idx) {
            if (!e_dst)      e_dst = d_in[i];
            else if (!e_src) e_src = d_in[i];
        }
        else if (!x)                           x = (const float*)d_in[i];
    }

    float* out = (float*)d_out;
    const int E = (int)E_ll;

    const int n4 = out_size / 4;
    init_kernel<<<(n4 + 255) / 256, 256>>>((float4*)out, n4,
                                           (const unsigned int*)e_dst,
                                           (const unsigned int*)e_src);

    const int blocks = (E + EDGES_PER_BLOCK - 1) / EDGES_PER_BLOCK;
    tp_scatter_kernel<<<blocks, 256>>>(x, edge_attr, edge_wt, e_dst, e_src, out, E);
}

// round 8
// speedup vs baseline: 1.5622x; 1.0111x over previous
#include <cuda_runtime.h>
#include <cstdint>

#define MUL 32
#define N_NODES 50000
#define E_FEAT 224           // 32 + 96 + 96
#define EDGES_PER_BLOCK 8    // 256 threads / 32

__device__ int g_idx_is_64;                  // 1 if index buffers are int64, 0 if int32
__device__ float g_xt[N_NODES * 4 * MUL];    // x transposed: [xs0(32)|x1a(32)|x1b(32)|x1c(32)] per node

__device__ __forceinline__ void red_add_v4(float* addr, float4 v) {
    asm volatile("red.global.add.v4.f32 [%0], {%1,%2,%3,%4};"
                 :: "l"(addr), "f"(v.x), "f"(v.y), "f"(v.z), "f"(v.w)
                 : "memory");
}

__device__ __forceinline__ long long load_index(const void* p, int e, int is64) {
    if (is64) return ((const long long*)p)[e];
    return (long long)(__ldcs((const int*)p + e));
}

// Fused: zero the output AND (thread 0 of block 0) detect index dtype.
__global__ void init_kernel(float4* __restrict__ out, int n4,
                            const unsigned int* __restrict__ dw,
                            const unsigned int* __restrict__ sw) {
    int i = blockIdx.x * blockDim.x + threadIdx.x;
    if (i < n4) out[i] = make_float4(0.f, 0.f, 0.f, 0.f);
    if (blockIdx.x == 0 && threadIdx.x == 0) {
        // int64 little-endian values < 50000 -> every odd 32-bit word is 0.
        int is64 = 1;
        #pragma unroll
        for (int k = 0; k < 32; k++) {
            if (dw[2 * k + 1] != 0u || sw[2 * k + 1] != 0u) { is64 = 0; break; }
        }
        g_idx_is_64 = is64;
    }
}

// One-shot transpose of x into SoA-ish layout; warp per node. Amortized over
// avg degree ~16: turns the per-edge 10-wavefront strided gather into 4.
__global__ __launch_bounds__(256)
void transpose_kernel(const float* __restrict__ x) {
    const int warp = threadIdx.x >> 5;
    const int lane = threadIdx.x & 31;
    const int n = blockIdx.x * EDGES_PER_BLOCK + warp;
    if (n >= N_NODES) return;
    const float* __restrict__ xr = x + (size_t)n * (4 * MUL);
    const float xs0 = xr[lane];
    const float x1a = xr[32 + lane * 3 + 0];
    const float x1b = xr[32 + lane * 3 + 1];
    const float x1c = xr[32 + lane * 3 + 2];
    float* __restrict__ xt = g_xt + (size_t)n * (4 * MUL);
    xt[lane]      = xs0;
    xt[32 + lane] = x1a;
    xt[64 + lane] = x1b;
    xt[96 + lane] = x1c;
}

__global__ __launch_bounds__(256)
void tp_scatter_kernel(const float* __restrict__ attr,
                       const float* __restrict__ w,
                       const void* __restrict__ edge_dst,
                       const void* __restrict__ edge_src,
                       float* __restrict__ out,
                       int E) {
    constexpr float INV_S2 = 0.70710678118654752f;
    constexpr float INV_S3 = 0.57735026918962576f;

    __shared__ float sf[EDGES_PER_BLOCK][E_FEAT];

    const int warp = threadIdx.x >> 5;
    const int lane = threadIdx.x & 31;
    const int e = blockIdx.x * EDGES_PER_BLOCK + warp;
    if (e >= E) return;

    const int is64 = g_idx_is_64;
    const long long s = load_index(edge_src, e, is64);
    const long long d = load_index(edge_dst, e, is64);
    // Safety guard (valid inputs always in range).
    if ((unsigned long long)s >= (unsigned long long)N_NODES ||
        (unsigned long long)d >= (unsigned long long)N_NODES) return;

    // x row from transposed layout: 4 fully coalesced 1-wavefront loads.
    const float* __restrict__ xr = g_xt + s * (4 * MUL);
    const float xs0 = __ldg(xr + lane);
    const float x1a = __ldg(xr + 32 + lane);
    const float x1b = __ldg(xr + 64 + lane);
    const float x1c = __ldg(xr + 96 + lane);

    // attr / weights streamed once: evict-first.
    const float4 a = __ldcs(reinterpret_cast<const float4*>(attr + (size_t)e * 4));

    const float* __restrict__ wr = w + (size_t)e * (5 * MUL);
    const float w0 = __ldcs(wr + lane);
    const float w1 = __ldcs(wr + 32 + lane);
    const float w2 = __ldcs(wr + 64 + lane);
    const float w3 = __ldcs(wr + 96 + lane);
    const float w4 = __ldcs(wr + 128 + lane);

    const float dot = x1a * a.y + x1b * a.z + x1c * a.w;

    const float o0  = INV_S2 * (w0 * xs0 * a.x + w3 * (INV_S3 * dot));
    const float o1a = INV_S2 * (w1 * xs0 * a.y + w2 * x1a * a.x);
    const float o1b = INV_S2 * (w1 * xs0 * a.z + w2 * x1b * a.x);
    const float o1c = INV_S2 * (w1 * xs0 * a.w + w2 * x1c * a.x);

    // cross(xs1, a1)
    const float c0 = x1b * a.w - x1c * a.z;
    const float c1 = x1c * a.y - x1a * a.w;
    const float c2 = x1a * a.z - x1b * a.y;
    const float o2a = INV_S2 * w4 * c0;
    const float o2b = INV_S2 * w4 * c1;
    const float o2c = INV_S2 * w4 * c2;

    // Stage outputs in output layout (conflict-free: 3u+i mod 32 is a bijection per i)
    sf[warp][lane]               = o0;
    sf[warp][32 + lane * 3 + 0]  = o1a;
    sf[warp][32 + lane * 3 + 1]  = o1b;
    sf[warp][32 + lane * 3 + 2]  = o1c;
    sf[warp][128 + lane * 3 + 0] = o2a;
    sf[warp][128 + lane * 3 + 1] = o2b;
    sf[warp][128 + lane * 3 + 2] = o2c;
    __syncwarp();

    float* __restrict__ ob = out + d * E_FEAT;   // d*896 bytes: 16B-aligned

    // 224 floats = 56 float4 vector-REDs
    float4 v0 = *reinterpret_cast<float4*>(&sf[warp][lane * 4]);
    red_add_v4(ob + lane * 4, v0);
    const int idx = lane + 32;
    if (idx < 56) {
        float4 v1 = *reinterpret_cast<float4*>(&sf[warp][idx * 4]);
        red_add_v4(ob + idx * 4, v1);
    }
}

extern "C" void kernel_launch(void* const* d_in, const int* in_sizes, int n_in,
                              void* d_out, int out_size) {
    // Identify inputs by element count (robust to harness input ordering):
    //   edge_weight : E*160 (largest), edge_attr : E*4, edge_dst/src : E (dst first), x : remainder
    const float* x = nullptr;
    const float* edge_attr = nullptr;
    const float* edge_wt = nullptr;
    const void* e_dst = nullptr;
    const void* e_src = nullptr;

    long long sz_w = 0;
    for (int i = 0; i < n_in; i++)
        if ((long long)in_sizes[i] > sz_w) sz_w = in_sizes[i];

    const long long E_ll = sz_w / 160;
    const long long sz_attr = E_ll * 4;
    const long long sz_idx  = E_ll;

    for (int i = 0; i < n_in; i++) {
        long long sz = in_sizes[i];
        if (sz == sz_w && !edge_wt)            edge_wt   = (const float*)d_in[i];
        else if (sz == sz_attr && !edge_attr)  edge_attr = (const float*)d_in[i];
        else if (sz == sz_idx) {
            if (!e_dst)      e_dst = d_in[i];
            else if (!e_src) e_src = d_in[i];
        }
        else if (!x)                           x = (const float*)d_in[i];
    }

    float* out = (float*)d_out;
    const int E = (int)E_ll;

    const int n4 = out_size / 4;
    init_kernel<<<(n4 + 255) / 256, 256>>>((float4*)out, n4,
                                           (const unsigned int*)e_dst,
                                           (const unsigned int*)e_src);
    transpose_kernel<<<(N_NODES + EDGES_PER_BLOCK - 1) / EDGES_PER_BLOCK, 256>>>(x);

    const int blocks = (E + EDGES_PER_BLOCK - 1) / EDGES_PER_BLOCK;
    tp_scatter_kernel<<<blocks, 256>>>(edge_attr, edge_wt, e_dst, e_src, out, E);
}